// round 4
// baseline (speedup 1.0000x reference)
#include <cuda_runtime.h>

#define B_  4
#define N_  16384
#define D_  256
#define M_  64
#define H_  8
#define S_  32          // split-K chunks for pooling (512 n each)

// ---------------- scratch (static device globals; no allocation) ----------------
__device__ float g_logits[(size_t)B_ * M_ * N_];      // [B][M][N]
__device__ float g_c[B_ * M_];                        // c = max + log(sumexp)
__device__ float g_part[(size_t)B_ * S_ * M_ * D_];   // split-K partials
__device__ float g_tokens[B_ * M_ * D_];
__device__ float g_qkv[B_ * M_ * 3 * D_];
__device__ float g_attn[B_ * M_ * D_];
__device__ float g_tokout[B_ * M_ * D_];

// ---------------- packed fp32x2 helpers ----------------
__device__ __forceinline__ void fma2(unsigned long long &c,
                                     const unsigned long long a,
                                     const unsigned long long b) {
    asm("fma.rn.f32x2 %0, %1, %2, %0;" : "+l"(c) : "l"(a), "l"(b));
}
__device__ __forceinline__ unsigned long long pack2(float x, float y) {
    unsigned long long r;
    asm("mov.b64 %0, {%1, %2};" : "=l"(r) : "f"(x), "f"(y));
    return r;
}
union F2U { unsigned long long u; float2 f; };

// Tile engine: acc[8 A-rows][2 B-pairs(4 floats)] over 32 k.
// As: [32][132]  A value j duplicated at columns 2j,2j+1
// Bs: [32][132]  plain
__device__ __forceinline__ void mma_tile(const float (*As)[132], const float (*Bs)[132],
                                         unsigned long long acc[8][2], int tn, int wm) {
#pragma unroll
    for (int kk = 0; kk < 32; kk++) {
        const ulonglong2* ap = (const ulonglong2*)&As[kk][wm * 16];
        ulonglong2 a0 = ap[0], a1 = ap[1], a2 = ap[2], a3 = ap[3];
        ulonglong2 bv = *(const ulonglong2*)&Bs[kk][tn * 4];
        fma2(acc[0][0], a0.x, bv.x); fma2(acc[0][1], a0.x, bv.y);
        fma2(acc[1][0], a0.y, bv.x); fma2(acc[1][1], a0.y, bv.y);
        fma2(acc[2][0], a1.x, bv.x); fma2(acc[2][1], a1.x, bv.y);
        fma2(acc[3][0], a1.y, bv.x); fma2(acc[3][1], a1.y, bv.y);
        fma2(acc[4][0], a2.x, bv.x); fma2(acc[4][1], a2.x, bv.y);
        fma2(acc[5][0], a2.y, bv.x); fma2(acc[5][1], a2.y, bv.y);
        fma2(acc[6][0], a3.x, bv.x); fma2(acc[6][1], a3.x, bv.y);
        fma2(acc[7][0], a3.y, bv.x); fma2(acc[7][1], a3.y, bv.y);
    }
}

// =====================================================================
// K1/K5/K6: C[64 x Ncols] = A[64 x 256] * B[Ncols x 256]^T (+ biases)
// grid: (Ncols/128, 1, B)
// =====================================================================
__global__ __launch_bounds__(256) void gemm64_nt(
    const float* __restrict__ A, const float* __restrict__ Bm, float* __restrict__ C,
    int ldc, size_t aStride, size_t bStride, size_t cStride,
    const float* __restrict__ rowBias, const float* __restrict__ colBias)
{
    const float* Ab = A + (size_t)blockIdx.z * aStride;
    const float* Bb = Bm + (size_t)blockIdx.z * bStride;
    float* Cb = C + (size_t)blockIdx.z * cStride;
    const int n0 = blockIdx.x * 128;

    __shared__ float As[32][132];
    __shared__ float Bs[32][132];

    const int tid = threadIdx.x;
    const int tn = tid & 31;
    const int wm = tid >> 5;

    unsigned long long acc[8][2];
#pragma unroll
    for (int i = 0; i < 8; i++) { acc[i][0] = 0ull; acc[i][1] = 0ull; }

    for (int k0 = 0; k0 < 256; k0 += 32) {
#pragma unroll
        for (int rep = 0; rep < 2; rep++) {               // A: 64m x 32k, dup
            int id = tid + rep * 256;
            int m = id >> 3;
            int kq = (id & 7) * 4;
            float4 v = *(const float4*)(Ab + (size_t)m * 256 + k0 + kq);
            *(unsigned long long*)&As[kq + 0][2 * m] = pack2(v.x, v.x);
            *(unsigned long long*)&As[kq + 1][2 * m] = pack2(v.y, v.y);
            *(unsigned long long*)&As[kq + 2][2 * m] = pack2(v.z, v.z);
            *(unsigned long long*)&As[kq + 3][2 * m] = pack2(v.w, v.w);
        }
#pragma unroll
        for (int rep = 0; rep < 4; rep++) {               // B: 128n x 32k
            int id = tid + rep * 256;
            int n = id >> 3;
            int kq = (id & 7) * 4;
            float4 v = *(const float4*)(Bb + (size_t)(n0 + n) * 256 + k0 + kq);
            Bs[kq + 0][n] = v.x; Bs[kq + 1][n] = v.y;
            Bs[kq + 2][n] = v.z; Bs[kq + 3][n] = v.w;
        }
        __syncthreads();
        mma_tile(As, Bs, acc, tn, wm);
        __syncthreads();
    }

    float cb0 = 0.f, cb1 = 0.f, cb2 = 0.f, cb3 = 0.f;
    if (colBias) {
        float4 cb = *(const float4*)(colBias + n0 + tn * 4);
        cb0 = cb.x; cb1 = cb.y; cb2 = cb.z; cb3 = cb.w;
    }
#pragma unroll
    for (int i = 0; i < 8; i++) {
        int m = wm * 8 + i;
        float rb = rowBias ? rowBias[m] : 0.f;
        F2U u0, u1; u0.u = acc[i][0]; u1.u = acc[i][1];
        float4 r;
        r.x = u0.f.x + rb + cb0;
        r.y = u0.f.y + rb + cb1;
        r.z = u1.f.x + rb + cb2;
        r.w = u1.f.y + rb + cb3;
        *(float4*)(Cb + (size_t)m * ldc + n0 + tn * 4) = r;
    }
}

// =====================================================================
// K2: per-(b,m) online softmax stats over N -> c = max + log(sumexp)
// =====================================================================
__global__ __launch_bounds__(256) void softmax_stats()
{
    const float* p = g_logits + (size_t)blockIdx.x * N_;
    const int t = threadIdx.x;
    float mx = -1e30f, sm = 0.f;
    for (int i = t * 4; i < N_; i += 1024) {
        float4 v = *(const float4*)(p + i);
        float a[4] = { v.x, v.y, v.z, v.w };
#pragma unroll
        for (int j = 0; j < 4; j++) {
            float nm = fmaxf(mx, a[j]);
            sm = sm * __expf(mx - nm) + __expf(a[j] - nm);
            mx = nm;
        }
    }
    __shared__ float smx[256], ssm[256];
    smx[t] = mx; ssm[t] = sm;
    __syncthreads();
    for (int s = 128; s > 0; s >>= 1) {
        if (t < s) {
            float m2 = smx[t + s], s2 = ssm[t + s];
            float nm = fmaxf(smx[t], m2);
            ssm[t] = ssm[t] * __expf(smx[t] - nm) + s2 * __expf(m2 - nm);
            smx[t] = nm;
        }
        __syncthreads();
    }
    if (t == 0) g_c[blockIdx.x] = smx[0] + __logf(ssm[0]);
}

// =====================================================================
// K3: split-K pooling partials. grid (2 d-tiles, 32 splits, 4 b)
// partial[b][s][m][d] = sum_{n in split} exp(l[b,m,n]-c[b,m]) * x[b,n,d]
// =====================================================================
__global__ __launch_bounds__(256) void pool_partial(const float* __restrict__ x)
{
    const int b = blockIdx.z, s = blockIdx.y;
    const int d0 = blockIdx.x * 128;
    const float* lg = g_logits + (size_t)b * M_ * N_;
    const float* xb = x + (size_t)b * N_ * D_;

    __shared__ float As[32][132];
    __shared__ float Bs[32][132];
    __shared__ float cs[64];

    const int tid = threadIdx.x;
    if (tid < 64) cs[tid] = g_c[b * 64 + tid];
    const int tn = tid & 31;
    const int wm = tid >> 5;

    unsigned long long acc[8][2];
#pragma unroll
    for (int i = 0; i < 8; i++) { acc[i][0] = 0ull; acc[i][1] = 0ull; }
    __syncthreads();

    for (int nc = 0; nc < 16; nc++) {
        const int kbase = s * 512 + nc * 32;
#pragma unroll
        for (int rep = 0; rep < 2; rep++) {       // weights: 64m x 32n, exp+dup
            int id = tid + rep * 256;
            int m = id >> 3;
            int kq = (id & 7) * 4;
            float4 v = *(const float4*)(lg + (size_t)m * N_ + kbase + kq);
            float cm = cs[m];
            float w0 = __expf(v.x - cm), w1 = __expf(v.y - cm);
            float w2 = __expf(v.z - cm), w3 = __expf(v.w - cm);
            *(unsigned long long*)&As[kq + 0][2 * m] = pack2(w0, w0);
            *(unsigned long long*)&As[kq + 1][2 * m] = pack2(w1, w1);
            *(unsigned long long*)&As[kq + 2][2 * m] = pack2(w2, w2);
            *(unsigned long long*)&As[kq + 3][2 * m] = pack2(w3, w3);
        }
#pragma unroll
        for (int rep = 0; rep < 4; rep++) {       // x: 32n x 128d direct
            int id = tid + rep * 256;
            int row = id >> 5;
            int dq = (id & 31) * 4;
            *(float4*)&Bs[row][dq] =
                *(const float4*)(xb + (size_t)(kbase + row) * D_ + d0 + dq);
        }
        __syncthreads();
        mma_tile(As, Bs, acc, tn, wm);
        __syncthreads();
    }

    float* P = g_part + (size_t)(b * S_ + s) * M_ * D_;
#pragma unroll
    for (int i = 0; i < 8; i++) {
        int m = wm * 8 + i;
        F2U u0, u1; u0.u = acc[i][0]; u1.u = acc[i][1];
        *(float4*)(P + (size_t)m * D_ + d0 + tn * 4) =
            make_float4(u0.f.x, u0.f.y, u1.f.x, u1.f.y);
    }
}

// K4: deterministic split-K reduce -> tokens
__global__ __launch_bounds__(256) void pool_reduce()
{
    int idx = blockIdx.x * 256 + threadIdx.x;     // < B*M*D = 65536
    int b = idx >> 14;
    int r = idx & 16383;
    const float* p = g_part + (size_t)b * S_ * (M_ * D_) + r;
    float s = 0.f;
#pragma unroll
    for (int i = 0; i < S_; i++) s += p[(size_t)i * (M_ * D_)];
    g_tokens[idx] = s;
}

// =====================================================================
// Attention over M=64 tokens, per (b,h). 32 blocks x 64 threads.
// =====================================================================
__global__ __launch_bounds__(64) void attn_kernel()
{
    const int b = blockIdx.x >> 3, h = blockIdx.x & 7;
    __shared__ float ks[64][33], vs[64][33];
    const int t = threadIdx.x;
    const float* base = g_qkv + (size_t)b * M_ * 768 + h * 32;
    const float* kr = base + (size_t)t * 768 + 256;
    const float* vr = base + (size_t)t * 768 + 512;
#pragma unroll
    for (int j = 0; j < 32; j++) { ks[t][j] = kr[j]; vs[t][j] = vr[j]; }
    const float scale = 0.17677669529663687f;     // 1/sqrt(32)
    float q[32];
    const float* qr = base + (size_t)t * 768;
#pragma unroll
    for (int j = 0; j < 32; j++) q[j] = qr[j] * scale;
    __syncthreads();

    float sc[64]; float mx = -1e30f;
#pragma unroll 4
    for (int j = 0; j < 64; j++) {
        float s = 0.f;
#pragma unroll
        for (int d = 0; d < 32; d++) s += q[d] * ks[j][d];
        sc[j] = s; mx = fmaxf(mx, s);
    }
    float sum = 0.f;
#pragma unroll 4
    for (int j = 0; j < 64; j++) { sc[j] = __expf(sc[j] - mx); sum += sc[j]; }
    float inv = 1.f / sum;
    float o[32];
#pragma unroll
    for (int d = 0; d < 32; d++) o[d] = 0.f;
#pragma unroll 4
    for (int j = 0; j < 64; j++) {
        float p = sc[j] * inv;
#pragma unroll
        for (int d = 0; d < 32; d++) o[d] += p * vs[j][d];
    }
    float* op = g_attn + (size_t)b * M_ * D_ + (size_t)t * D_ + h * 32;
#pragma unroll
    for (int d = 0; d < 32; d++) op[d] = o[d];
}

// =====================================================================
// K7: unpooling. out[b,n,d] = sum_m exp(l[b,m,n]-c[b,m]) * tokout[b,m,d]
// tile 64n x 128d, K=64.  grid (2, 256, 4)
// =====================================================================
__global__ __launch_bounds__(256) void unpool_kernel(float* __restrict__ out)
{
    const int b = blockIdx.z;
    const int n0 = blockIdx.y * 64;
    const int d0 = blockIdx.x * 128;
    const float* lg = g_logits + (size_t)b * M_ * N_;

    __shared__ float As[32][132];   // [k=m][2n] dup weights
    __shared__ float Bs[32][132];   // [k=m][d]
    __shared__ float cs[64];

    const int tid = threadIdx.x;
    if (tid < 64) cs[tid] = g_c[b * 64 + tid];
    const int tn = tid & 31;
    const int wm = tid >> 5;

    unsigned long long acc[8][2];
#pragma unroll
    for (int i = 0; i < 8; i++) { acc[i][0] = 0ull; acc[i][1] = 0ull; }
    __syncthreads();

    for (int k0 = 0; k0 < 64; k0 += 32) {
#pragma unroll
        for (int rep = 0; rep < 2; rep++) {       // weights: 32k x 64n, exp+dup
            int id = tid + rep * 256;
            int k = id >> 4;                      // 0..31
            int n4 = (id & 15) * 4;               // 0..60
            float4 v = *(const float4*)(lg + (size_t)(k0 + k) * N_ + n0 + n4);
            float cm = cs[k0 + k];
            float w0 = __expf(v.x - cm), w1 = __expf(v.y - cm);
            float w2 = __expf(v.z - cm), w3 = __expf(v.w - cm);
            *(unsigned long long*)&As[k][2 * (n4 + 0)] = pack2(w0, w0);
            *(unsigned long long*)&As[k][2 * (n4 + 1)] = pack2(w1, w1);
            *(unsigned long long*)&As[k][2 * (n4 + 2)] = pack2(w2, w2);
            *(unsigned long long*)&As[k][2 * (n4 + 3)] = pack2(w3, w3);
        }
#pragma unroll
        for (int rep = 0; rep < 4; rep++) {       // tokout: 32k x 128d
            int id = tid + rep * 256;
            int row = id >> 5;
            int dq = (id & 31) * 4;
            *(float4*)&Bs[row][dq] =
                *(const float4*)(g_tokout + ((size_t)b * M_ + k0 + row) * D_ + d0 + dq);
        }
        __syncthreads();
        mma_tile(As, Bs, acc, tn, wm);
        __syncthreads();
    }

#pragma unroll
    for (int i = 0; i < 8; i++) {
        int n = n0 + wm * 8 + i;
        F2U u0, u1; u0.u = acc[i][0]; u1.u = acc[i][1];
        *(float4*)(out + ((size_t)b * N_ + n) * D_ + d0 + tn * 4) =
            make_float4(u0.f.x, u0.f.y, u1.f.x, u1.f.y);
    }
}

// =====================================================================
extern "C" void kernel_launch(void* const* d_in, const int* in_sizes, int n_in,
                              void* d_out, int out_size)
{
    const float* x    = (const float*)d_in[0];
    const float* Ws   = (const float*)d_in[1];
    const float* bs   = (const float*)d_in[2];
    const float* Wqkv = (const float*)d_in[3];
    const float* Wo   = (const float*)d_in[4];
    const float* bo   = (const float*)d_in[5];
    float* out = (float*)d_out;

    float *lg, *tok, *qkv, *att, *tko;
    cudaGetSymbolAddress((void**)&lg,  g_logits);
    cudaGetSymbolAddress((void**)&tok, g_tokens);
    cudaGetSymbolAddress((void**)&qkv, g_qkv);
    cudaGetSymbolAddress((void**)&att, g_attn);
    cudaGetSymbolAddress((void**)&tko, g_tokout);

    // K1: logits[b][m][n] = x . Ws^T + bs   (A=Ws 64x256, B=x[b] 16384x256)
    gemm64_nt<<<dim3(N_ / 128, 1, B_), 256>>>(
        Ws, x, lg, N_, 0, (size_t)N_ * D_, (size_t)M_ * N_, bs, nullptr);
    // K2: softmax stats
    softmax_stats<<<B_ * M_, 256>>>();
    // K3/K4: pooling
    pool_partial<<<dim3(2, S_, B_), 256>>>(x);
    pool_reduce<<<256, 256>>>();
    // K5: qkv = tokens . Wqkv^T  (Ncols=768)
    gemm64_nt<<<dim3(6, 1, B_), 256>>>(
        tok, Wqkv, qkv, 768, (size_t)M_ * D_, 0, (size_t)M_ * 768, nullptr, nullptr);
    // attention
    attn_kernel<<<B_ * H_, 64>>>();
    // K6: token_out = attn . Wo^T + bo
    gemm64_nt<<<dim3(2, 1, B_), 256>>>(
        att, Wo, tko, D_, (size_t)M_ * D_, 0, (size_t)M_ * D_, nullptr, bo);
    // K7: unpool
    unpool_kernel<<<dim3(2, N_ / 64, B_), 256>>>(out);
}

// round 5
// speedup vs baseline: 1.5162x; 1.5162x over previous
#include <cuda_runtime.h>

#define B_  4
#define N_  16384
#define D_  256
#define M_  64
#define H_  8
#define S2_ 64          // split-K chunks for pooling (256 n each)

// ---------------- scratch (static device globals; no allocation) ----------------
__device__ float g_logits[(size_t)B_ * M_ * N_];        // [B][M][N]
__device__ float g_c[B_ * M_];                          // c = max + log(sumexp)
__device__ float g_part[(size_t)B_ * S2_ * M_ * D_];    // split-K partials (16.8MB)
__device__ float g_tokens[B_ * M_ * D_];
__device__ float g_qkv[B_ * M_ * 3 * D_];
__device__ float g_attn[B_ * M_ * D_];
__device__ float g_tokout[B_ * M_ * D_];

// ---------------- packed fp32x2 helpers ----------------
__device__ __forceinline__ void fma2(unsigned long long &c,
                                     const unsigned long long a,
                                     const unsigned long long b) {
    asm("fma.rn.f32x2 %0, %1, %2, %0;" : "+l"(c) : "l"(a), "l"(b));
}
__device__ __forceinline__ unsigned long long pack2(float x, float y) {
    unsigned long long r;
    asm("mov.b64 %0, {%1, %2};" : "=l"(r) : "f"(x), "f"(y));
    return r;
}
union F2U { unsigned long long u; float2 f; };

// ============= wide tile engine: 64 rows x 256 cols, 8x8 per thread ==========
// As: [16][132]  row value j duplicated at cols 2j,2j+1 (reads are warp-broadcast)
// Bs: [16][260]  plain, cols 0..255
// thread: tm = tid>>5 (8 row-groups), tn = tid&31 (col quads at tn*4 and 128+tn*4)
__device__ __forceinline__ void mma_wide(const float (*As)[132], const float (*Bs)[260],
                                         unsigned long long acc[8][4], int tn, int tm) {
#pragma unroll
    for (int kk = 0; kk < 16; kk++) {
        const ulonglong2* ap = (const ulonglong2*)&As[kk][tm * 16];
        ulonglong2 a0 = ap[0], a1 = ap[1], a2 = ap[2], a3 = ap[3];
        ulonglong2 b0 = *(const ulonglong2*)&Bs[kk][tn * 4];
        ulonglong2 b1 = *(const ulonglong2*)&Bs[kk][128 + tn * 4];
        fma2(acc[0][0], a0.x, b0.x); fma2(acc[0][1], a0.x, b0.y);
        fma2(acc[0][2], a0.x, b1.x); fma2(acc[0][3], a0.x, b1.y);
        fma2(acc[1][0], a0.y, b0.x); fma2(acc[1][1], a0.y, b0.y);
        fma2(acc[1][2], a0.y, b1.x); fma2(acc[1][3], a0.y, b1.y);
        fma2(acc[2][0], a1.x, b0.x); fma2(acc[2][1], a1.x, b0.y);
        fma2(acc[2][2], a1.x, b1.x); fma2(acc[2][3], a1.x, b1.y);
        fma2(acc[3][0], a1.y, b0.x); fma2(acc[3][1], a1.y, b0.y);
        fma2(acc[3][2], a1.y, b1.x); fma2(acc[3][3], a1.y, b1.y);
        fma2(acc[4][0], a2.x, b0.x); fma2(acc[4][1], a2.x, b0.y);
        fma2(acc[4][2], a2.x, b1.x); fma2(acc[4][3], a2.x, b1.y);
        fma2(acc[5][0], a2.y, b0.x); fma2(acc[5][1], a2.y, b0.y);
        fma2(acc[5][2], a2.y, b1.x); fma2(acc[5][3], a2.y, b1.y);
        fma2(acc[6][0], a3.x, b0.x); fma2(acc[6][1], a3.x, b0.y);
        fma2(acc[6][2], a3.x, b1.x); fma2(acc[6][3], a3.x, b1.y);
        fma2(acc[7][0], a3.y, b0.x); fma2(acc[7][1], a3.y, b0.y);
        fma2(acc[7][2], a3.y, b1.x); fma2(acc[7][3], a3.y, b1.y);
    }
}

// =====================================================================
// K1: logits C[64 x Ncols] = A[64 x 256] * B[Ncols x 256]^T (+rowBias)
// tile 64 x 256, grid (Ncols/256, 1, B)
// =====================================================================
__global__ __launch_bounds__(256) void gemm64_wide(
    const float* __restrict__ A, const float* __restrict__ Bm, float* __restrict__ C,
    int ldc, size_t aStride, size_t bStride, size_t cStride,
    const float* __restrict__ rowBias)
{
    const float* Ab = A + (size_t)blockIdx.z * aStride;
    const float* Bb = Bm + (size_t)blockIdx.z * bStride;
    float* Cb = C + (size_t)blockIdx.z * cStride;
    const int n0 = blockIdx.x * 256;

    __shared__ float As[16][132];
    __shared__ float Bs[16][260];

    const int tid = threadIdx.x;
    const int tn = tid & 31;
    const int tm = tid >> 5;

    unsigned long long acc[8][4];
#pragma unroll
    for (int i = 0; i < 8; i++)
#pragma unroll
        for (int j = 0; j < 4; j++) acc[i][j] = 0ull;

    for (int k0 = 0; k0 < 256; k0 += 16) {
        {   // A: 64m x 16k, dup  (1 rep: 256 float4)
            int m = tid >> 2;
            int kq = (tid & 3) * 4;
            float4 v = *(const float4*)(Ab + (size_t)m * 256 + k0 + kq);
            *(unsigned long long*)&As[kq + 0][2 * m] = pack2(v.x, v.x);
            *(unsigned long long*)&As[kq + 1][2 * m] = pack2(v.y, v.y);
            *(unsigned long long*)&As[kq + 2][2 * m] = pack2(v.z, v.z);
            *(unsigned long long*)&As[kq + 3][2 * m] = pack2(v.w, v.w);
        }
#pragma unroll
        for (int rep = 0; rep < 4; rep++) {       // B: 256n x 16k, transpose
            int id = tid + rep * 256;
            int n = id >> 2;
            int kq = (id & 3) * 4;
            float4 v = *(const float4*)(Bb + (size_t)(n0 + n) * 256 + k0 + kq);
            Bs[kq + 0][n] = v.x; Bs[kq + 1][n] = v.y;
            Bs[kq + 2][n] = v.z; Bs[kq + 3][n] = v.w;
        }
        __syncthreads();
        mma_wide(As, Bs, acc, tn, tm);
        __syncthreads();
    }

#pragma unroll
    for (int i = 0; i < 8; i++) {
        int m = tm * 8 + i;
        float rb = rowBias ? rowBias[m] : 0.f;
        F2U u0, u1, u2, u3;
        u0.u = acc[i][0]; u1.u = acc[i][1]; u2.u = acc[i][2]; u3.u = acc[i][3];
        *(float4*)(Cb + (size_t)m * ldc + n0 + tn * 4) =
            make_float4(u0.f.x + rb, u0.f.y + rb, u1.f.x + rb, u1.f.y + rb);
        *(float4*)(Cb + (size_t)m * ldc + n0 + 128 + tn * 4) =
            make_float4(u2.f.x + rb, u2.f.y + rb, u3.f.x + rb, u3.f.y + rb);
    }
}

// =====================================================================
// K2: per-(b,m) online softmax stats over N -> c = max + log(sumexp)
// =====================================================================
__global__ __launch_bounds__(256) void softmax_stats()
{
    const float* p = g_logits + (size_t)blockIdx.x * N_;
    const int t = threadIdx.x;
    float mx = -1e30f, sm = 0.f;
    for (int i = t * 4; i < N_; i += 1024) {
        float4 v = *(const float4*)(p + i);
        float a[4] = { v.x, v.y, v.z, v.w };
#pragma unroll
        for (int j = 0; j < 4; j++) {
            float nm = fmaxf(mx, a[j]);
            sm = sm * __expf(mx - nm) + __expf(a[j] - nm);
            mx = nm;
        }
    }
    __shared__ float smx[256], ssm[256];
    smx[t] = mx; ssm[t] = sm;
    __syncthreads();
    for (int s = 128; s > 0; s >>= 1) {
        if (t < s) {
            float m2 = smx[t + s], s2 = ssm[t + s];
            float nm = fmaxf(smx[t], m2);
            ssm[t] = ssm[t] * __expf(smx[t] - nm) + s2 * __expf(m2 - nm);
            smx[t] = nm;
        }
        __syncthreads();
    }
    if (t == 0) g_c[blockIdx.x] = smx[0] + __logf(ssm[0]);
}

// =====================================================================
// K3: split-K pooling partials. grid (64 splits, 1, 4 b), full D=256 tile
// partial[b][s][m][d] = sum_{n in 256-split} exp(l[b,m,n]-c[b,m]) * x[b,n,d]
// =====================================================================
__global__ __launch_bounds__(256) void pool_partial(const float* __restrict__ x)
{
    const int b = blockIdx.z, s = blockIdx.x;
    const float* lg = g_logits + (size_t)b * M_ * N_;
    const float* xb = x + (size_t)b * N_ * D_;

    __shared__ float As[16][132];
    __shared__ float Bs[16][260];
    __shared__ float cs[64];

    const int tid = threadIdx.x;
    if (tid < 64) cs[tid] = g_c[b * 64 + tid];
    const int tn = tid & 31;
    const int tm = tid >> 5;

    unsigned long long acc[8][4];
#pragma unroll
    for (int i = 0; i < 8; i++)
#pragma unroll
        for (int j = 0; j < 4; j++) acc[i][j] = 0ull;
    __syncthreads();

    for (int nc = 0; nc < 16; nc++) {
        const int kbase = s * 256 + nc * 16;
        {   // weights: 64m x 16n, exp + dup
            int m = tid >> 2;
            int kq = (tid & 3) * 4;
            float4 v = *(const float4*)(lg + (size_t)m * N_ + kbase + kq);
            float cm = cs[m];
            float w0 = __expf(v.x - cm), w1 = __expf(v.y - cm);
            float w2 = __expf(v.z - cm), w3 = __expf(v.w - cm);
            *(unsigned long long*)&As[kq + 0][2 * m] = pack2(w0, w0);
            *(unsigned long long*)&As[kq + 1][2 * m] = pack2(w1, w1);
            *(unsigned long long*)&As[kq + 2][2 * m] = pack2(w2, w2);
            *(unsigned long long*)&As[kq + 3][2 * m] = pack2(w3, w3);
        }
#pragma unroll
        for (int rep = 0; rep < 4; rep++) {       // x: 16n x 256d, direct
            int id = tid + rep * 256;
            int row = id >> 6;
            int dq = (id & 63) * 4;
            *(float4*)&Bs[row][dq] =
                *(const float4*)(xb + (size_t)(kbase + row) * D_ + dq);
        }
        __syncthreads();
        mma_wide(As, Bs, acc, tn, tm);
        __syncthreads();
    }

    float* P = g_part + (size_t)(b * S2_ + s) * M_ * D_;
#pragma unroll
    for (int i = 0; i < 8; i++) {
        int m = tm * 8 + i;
        F2U u0, u1, u2, u3;
        u0.u = acc[i][0]; u1.u = acc[i][1]; u2.u = acc[i][2]; u3.u = acc[i][3];
        *(float4*)(P + (size_t)m * D_ + tn * 4) =
            make_float4(u0.f.x, u0.f.y, u1.f.x, u1.f.y);
        *(float4*)(P + (size_t)m * D_ + 128 + tn * 4) =
            make_float4(u2.f.x, u2.f.y, u3.f.x, u3.f.y);
    }
}

// K4: deterministic split-K reduce -> tokens (vectorized)
__global__ __launch_bounds__(256) void pool_reduce()
{
    int idx4 = blockIdx.x * 256 + threadIdx.x;    // < B*M*D/4 = 16384
    int b = idx4 >> 12;
    int r4 = idx4 & 4095;
    const float4* p = (const float4*)(g_part + (size_t)b * S2_ * (M_ * D_)) + r4;
    float4 s = make_float4(0.f, 0.f, 0.f, 0.f);
#pragma unroll
    for (int i = 0; i < S2_; i++) {
        float4 v = p[(size_t)i * (M_ * D_ / 4)];
        s.x += v.x; s.y += v.y; s.z += v.z; s.w += v.w;
    }
    ((float4*)g_tokens)[idx4] = s;
}

// =====================================================================
// K5/K6 narrow GEMM (64x128 tile) for qkv / out-proj
// =====================================================================
__device__ __forceinline__ void mma_tile(const float (*As)[132], const float (*Bs)[132],
                                         unsigned long long acc[8][2], int tn, int wm) {
#pragma unroll
    for (int kk = 0; kk < 32; kk++) {
        const ulonglong2* ap = (const ulonglong2*)&As[kk][wm * 16];
        ulonglong2 a0 = ap[0], a1 = ap[1], a2 = ap[2], a3 = ap[3];
        ulonglong2 bv = *(const ulonglong2*)&Bs[kk][tn * 4];
        fma2(acc[0][0], a0.x, bv.x); fma2(acc[0][1], a0.x, bv.y);
        fma2(acc[1][0], a0.y, bv.x); fma2(acc[1][1], a0.y, bv.y);
        fma2(acc[2][0], a1.x, bv.x); fma2(acc[2][1], a1.x, bv.y);
        fma2(acc[3][0], a1.y, bv.x); fma2(acc[3][1], a1.y, bv.y);
        fma2(acc[4][0], a2.x, bv.x); fma2(acc[4][1], a2.x, bv.y);
        fma2(acc[5][0], a2.y, bv.x); fma2(acc[5][1], a2.y, bv.y);
        fma2(acc[6][0], a3.x, bv.x); fma2(acc[6][1], a3.x, bv.y);
        fma2(acc[7][0], a3.y, bv.x); fma2(acc[7][1], a3.y, bv.y);
    }
}

__global__ __launch_bounds__(256) void gemm64_nt(
    const float* __restrict__ A, const float* __restrict__ Bm, float* __restrict__ C,
    int ldc, size_t aStride, size_t bStride, size_t cStride,
    const float* __restrict__ rowBias, const float* __restrict__ colBias)
{
    const float* Ab = A + (size_t)blockIdx.z * aStride;
    const float* Bb = Bm + (size_t)blockIdx.z * bStride;
    float* Cb = C + (size_t)blockIdx.z * cStride;
    const int n0 = blockIdx.x * 128;

    __shared__ float As[32][132];
    __shared__ float Bs[32][132];

    const int tid = threadIdx.x;
    const int tn = tid & 31;
    const int wm = tid >> 5;

    unsigned long long acc[8][2];
#pragma unroll
    for (int i = 0; i < 8; i++) { acc[i][0] = 0ull; acc[i][1] = 0ull; }

    for (int k0 = 0; k0 < 256; k0 += 32) {
#pragma unroll
        for (int rep = 0; rep < 2; rep++) {
            int id = tid + rep * 256;
            int m = id >> 3;
            int kq = (id & 7) * 4;
            float4 v = *(const float4*)(Ab + (size_t)m * 256 + k0 + kq);
            *(unsigned long long*)&As[kq + 0][2 * m] = pack2(v.x, v.x);
            *(unsigned long long*)&As[kq + 1][2 * m] = pack2(v.y, v.y);
            *(unsigned long long*)&As[kq + 2][2 * m] = pack2(v.z, v.z);
            *(unsigned long long*)&As[kq + 3][2 * m] = pack2(v.w, v.w);
        }
#pragma unroll
        for (int rep = 0; rep < 4; rep++) {
            int id = tid + rep * 256;
            int n = id >> 3;
            int kq = (id & 7) * 4;
            float4 v = *(const float4*)(Bb + (size_t)(n0 + n) * 256 + k0 + kq);
            Bs[kq + 0][n] = v.x; Bs[kq + 1][n] = v.y;
            Bs[kq + 2][n] = v.z; Bs[kq + 3][n] = v.w;
        }
        __syncthreads();
        mma_tile(As, Bs, acc, tn, wm);
        __syncthreads();
    }

    float cb0 = 0.f, cb1 = 0.f, cb2 = 0.f, cb3 = 0.f;
    if (colBias) {
        float4 cb = *(const float4*)(colBias + n0 + tn * 4);
        cb0 = cb.x; cb1 = cb.y; cb2 = cb.z; cb3 = cb.w;
    }
#pragma unroll
    for (int i = 0; i < 8; i++) {
        int m = wm * 8 + i;
        float rb = rowBias ? rowBias[m] : 0.f;
        F2U u0, u1; u0.u = acc[i][0]; u1.u = acc[i][1];
        *(float4*)(Cb + (size_t)m * ldc + n0 + tn * 4) =
            make_float4(u0.f.x + rb + cb0, u0.f.y + rb + cb1,
                        u1.f.x + rb + cb2, u1.f.y + rb + cb3);
    }
}

// =====================================================================
// Attention over M=64 tokens, per (b,h). 32 blocks x 64 threads. Fully unrolled.
// =====================================================================
__global__ __launch_bounds__(64) void attn_kernel()
{
    const int b = blockIdx.x >> 3, h = blockIdx.x & 7;
    __shared__ float ks[64][33], vs[64][33];
    const int t = threadIdx.x;
    const float* base = g_qkv + (size_t)b * M_ * 768 + h * 32;
    const float* kr = base + (size_t)t * 768 + 256;
    const float* vr = base + (size_t)t * 768 + 512;
#pragma unroll
    for (int j = 0; j < 32; j++) { ks[t][j] = kr[j]; vs[t][j] = vr[j]; }
    const float scale = 0.17677669529663687f;     // 1/sqrt(32)
    float q[32];
    const float* qr = base + (size_t)t * 768;
#pragma unroll
    for (int j = 0; j < 32; j++) q[j] = qr[j] * scale;
    __syncthreads();

    float sc[64]; float mx = -1e30f;
#pragma unroll
    for (int j = 0; j < 64; j++) {
        float s = 0.f;
#pragma unroll
        for (int d = 0; d < 32; d++) s += q[d] * ks[j][d];
        sc[j] = s; mx = fmaxf(mx, s);
    }
    float sum = 0.f;
#pragma unroll
    for (int j = 0; j < 64; j++) { sc[j] = __expf(sc[j] - mx); sum += sc[j]; }
    float inv = 1.f / sum;
    float o[32];
#pragma unroll
    for (int d = 0; d < 32; d++) o[d] = 0.f;
#pragma unroll
    for (int j = 0; j < 64; j++) {
        float p = sc[j] * inv;
#pragma unroll
        for (int d = 0; d < 32; d++) o[d] += p * vs[j][d];
    }
    float* op = g_attn + (size_t)b * M_ * D_ + (size_t)t * D_ + h * 32;
#pragma unroll
    for (int d = 0; d < 32; d++) op[d] = o[d];
}

// =====================================================================
// K7: unpooling. out[b,n,d] = sum_m exp(l[b,m,n]-c[b,m]) * tokout[b,m,d]
// tile 64n x 256d, K=64.  grid (256, 1, 4)
// =====================================================================
__global__ __launch_bounds__(256) void unpool_kernel(float* __restrict__ out)
{
    const int b = blockIdx.z;
    const int n0 = blockIdx.x * 64;
    const float* lg = g_logits + (size_t)b * M_ * N_;

    __shared__ float As[16][132];   // [k=m][2n dup]
    __shared__ float Bs[16][260];   // [k=m][d]
    __shared__ float cs[64];

    const int tid = threadIdx.x;
    if (tid < 64) cs[tid] = g_c[b * 64 + tid];
    const int tn = tid & 31;
    const int tm = tid >> 5;

    unsigned long long acc[8][4];
#pragma unroll
    for (int i = 0; i < 8; i++)
#pragma unroll
        for (int j = 0; j < 4; j++) acc[i][j] = 0ull;
    __syncthreads();

    for (int k0 = 0; k0 < 64; k0 += 16) {
        {   // weights: 16k(m) x 64n, exp + dup (1 rep)
            int mrow = tid >> 4;                  // 0..15
            int n4 = (tid & 15) * 4;              // 0..60
            float4 v = *(const float4*)(lg + (size_t)(k0 + mrow) * N_ + n0 + n4);
            float cm = cs[k0 + mrow];
            float w0 = __expf(v.x - cm), w1 = __expf(v.y - cm);
            float w2 = __expf(v.z - cm), w3 = __expf(v.w - cm);
            *(unsigned long long*)&As[mrow][2 * (n4 + 0)] = pack2(w0, w0);
            *(unsigned long long*)&As[mrow][2 * (n4 + 1)] = pack2(w1, w1);
            *(unsigned long long*)&As[mrow][2 * (n4 + 2)] = pack2(w2, w2);
            *(unsigned long long*)&As[mrow][2 * (n4 + 3)] = pack2(w3, w3);
        }
#pragma unroll
        for (int rep = 0; rep < 4; rep++) {       // tokout: 16k x 256d direct
            int id = tid + rep * 256;
            int row = id >> 6;
            int dq = (id & 63) * 4;
            *(float4*)&Bs[row][dq] =
                *(const float4*)(g_tokout + ((size_t)b * M_ + k0 + row) * D_ + dq);
        }
        __syncthreads();
        mma_wide(As, Bs, acc, tn, tm);
        __syncthreads();
    }

#pragma unroll
    for (int i = 0; i < 8; i++) {
        int n = n0 + tm * 8 + i;
        F2U u0, u1, u2, u3;
        u0.u = acc[i][0]; u1.u = acc[i][1]; u2.u = acc[i][2]; u3.u = acc[i][3];
        *(float4*)(out + ((size_t)b * N_ + n) * D_ + tn * 4) =
            make_float4(u0.f.x, u0.f.y, u1.f.x, u1.f.y);
        *(float4*)(out + ((size_t)b * N_ + n) * D_ + 128 + tn * 4) =
            make_float4(u2.f.x, u2.f.y, u3.f.x, u3.f.y);
    }
}

// =====================================================================
extern "C" void kernel_launch(void* const* d_in, const int* in_sizes, int n_in,
                              void* d_out, int out_size)
{
    const float* x    = (const float*)d_in[0];
    const float* Ws   = (const float*)d_in[1];
    const float* bs   = (const float*)d_in[2];
    const float* Wqkv = (const float*)d_in[3];
    const float* Wo   = (const float*)d_in[4];
    const float* bo   = (const float*)d_in[5];
    float* out = (float*)d_out;

    float *lg, *tok, *qkv, *att, *tko;
    cudaGetSymbolAddress((void**)&lg,  g_logits);
    cudaGetSymbolAddress((void**)&tok, g_tokens);
    cudaGetSymbolAddress((void**)&qkv, g_qkv);
    cudaGetSymbolAddress((void**)&att, g_attn);
    cudaGetSymbolAddress((void**)&tko, g_tokout);

    // K1: logits[b][m][n] = Ws . x[b]^T + bs   (wide tile)
    gemm64_wide<<<dim3(N_ / 256, 1, B_), 256>>>(
        Ws, x, lg, N_, 0, (size_t)N_ * D_, (size_t)M_ * N_, bs);
    // K2: softmax stats
    softmax_stats<<<B_ * M_, 256>>>();
    // K3/K4: pooling
    pool_partial<<<dim3(S2_, 1, B_), 256>>>(x);
    pool_reduce<<<64, 256>>>();
    // K5: qkv = tokens . Wqkv^T
    gemm64_nt<<<dim3(6, 1, B_), 256>>>(
        tok, Wqkv, qkv, 768, (size_t)M_ * D_, 0, (size_t)M_ * 768, nullptr, nullptr);
    // attention
    attn_kernel<<<B_ * H_, 64>>>();
    // K6: token_out = attn . Wo^T + bo
    gemm64_nt<<<dim3(2, 1, B_), 256>>>(
        att, Wo, tko, D_, (size_t)M_ * D_, 0, (size_t)M_ * D_, nullptr, bo);
    // K7: unpool
    unpool_kernel<<<dim3(N_ / 64, 1, B_), 256>>>(out);
}

// round 6
// speedup vs baseline: 1.5852x; 1.0455x over previous
#include <cuda_runtime.h>

#define B_  4
#define N_  16384
#define D_  256
#define M_  64
#define H_  8
#define S2_ 32          // split-K chunks for pooling (512 n each)

// ---------------- scratch (static device globals; no allocation) ----------------
__device__ float g_logits[(size_t)B_ * M_ * N_];        // [B][M][N]
__device__ float g_c[B_ * M_];                          // c = max + log(sumexp)
__device__ float g_part[(size_t)B_ * S2_ * M_ * D_];    // split-K partials (8.4MB)
__device__ float g_tokens[B_ * M_ * D_];
__device__ float g_qkv[B_ * M_ * 3 * D_];
__device__ float g_attn[B_ * M_ * D_];
__device__ float g_tokout[B_ * M_ * D_];

// ---------------- packed fp32x2 helpers ----------------
__device__ __forceinline__ void fma2(unsigned long long &c,
                                     const unsigned long long a,
                                     const unsigned long long b) {
    asm("fma.rn.f32x2 %0, %1, %2, %0;" : "+l"(c) : "l"(a), "l"(b));
}
__device__ __forceinline__ unsigned long long pack2(float x, float y) {
    unsigned long long r;
    asm("mov.b64 %0, {%1, %2};" : "=l"(r) : "f"(x), "f"(y));
    return r;
}
union F2U { unsigned long long u; float2 f; };

// ============= wide tile engine: 64 rows x 256 cols, 8x8 per thread ==========
// As: [16][132]  row value j duplicated at cols 2j,2j+1 (warp-broadcast reads)
// Bs: [16][260]  plain
__device__ __forceinline__ void mma_wide(const float (*As)[132], const float (*Bs)[260],
                                         unsigned long long acc[8][4], int tn, int tm) {
#pragma unroll
    for (int kk = 0; kk < 16; kk++) {
        const ulonglong2* ap = (const ulonglong2*)&As[kk][tm * 16];
        ulonglong2 a0 = ap[0], a1 = ap[1], a2 = ap[2], a3 = ap[3];
        ulonglong2 b0 = *(const ulonglong2*)&Bs[kk][tn * 4];
        ulonglong2 b1 = *(const ulonglong2*)&Bs[kk][128 + tn * 4];
        fma2(acc[0][0], a0.x, b0.x); fma2(acc[0][1], a0.x, b0.y);
        fma2(acc[0][2], a0.x, b1.x); fma2(acc[0][3], a0.x, b1.y);
        fma2(acc[1][0], a0.y, b0.x); fma2(acc[1][1], a0.y, b0.y);
        fma2(acc[1][2], a0.y, b1.x); fma2(acc[1][3], a0.y, b1.y);
        fma2(acc[2][0], a1.x, b0.x); fma2(acc[2][1], a1.x, b0.y);
        fma2(acc[2][2], a1.x, b1.x); fma2(acc[2][3], a1.x, b1.y);
        fma2(acc[3][0], a1.y, b0.x); fma2(acc[3][1], a1.y, b0.y);
        fma2(acc[3][2], a1.y, b1.x); fma2(acc[3][3], a1.y, b1.y);
        fma2(acc[4][0], a2.x, b0.x); fma2(acc[4][1], a2.x, b0.y);
        fma2(acc[4][2], a2.x, b1.x); fma2(acc[4][3], a2.x, b1.y);
        fma2(acc[5][0], a2.y, b0.x); fma2(acc[5][1], a2.y, b0.y);
        fma2(acc[5][2], a2.y, b1.x); fma2(acc[5][3], a2.y, b1.y);
        fma2(acc[6][0], a3.x, b0.x); fma2(acc[6][1], a3.x, b0.y);
        fma2(acc[6][2], a3.x, b1.x); fma2(acc[6][3], a3.x, b1.y);
        fma2(acc[7][0], a3.y, b0.x); fma2(acc[7][1], a3.y, b0.y);
        fma2(acc[7][2], a3.y, b1.x); fma2(acc[7][3], a3.y, b1.y);
    }
}

// =====================================================================
// K1: logits C[64 x Ncols] = A[64 x 256] * B[Ncols x 256]^T (+rowBias)
// pipelined; tile 64 x 256; grid (Ncols/256, 1, B)
// =====================================================================
__global__ __launch_bounds__(256) void gemm64_wide(
    const float* __restrict__ A, const float* __restrict__ Bm, float* __restrict__ C,
    int ldc, size_t aStride, size_t bStride, size_t cStride,
    const float* __restrict__ rowBias)
{
    const float* Ab = A + (size_t)blockIdx.z * aStride;
    const float* Bb = Bm + (size_t)blockIdx.z * bStride;
    float* Cb = C + (size_t)blockIdx.z * cStride;
    const int n0 = blockIdx.x * 256;

    __shared__ float As[16][132];
    __shared__ float Bs[16][260];

    const int tid = threadIdx.x;
    const int tn = tid & 31;
    const int tm = tid >> 5;
    // A-load coords (1 float4/thread)
    const int am = tid >> 2, akq = (tid & 3) * 4;
    // B-load coords (4 float4/thread)
    const int bn0 = tid >> 2, bkq = (tid & 3) * 4;

    unsigned long long acc[8][4];
#pragma unroll
    for (int i = 0; i < 8; i++)
#pragma unroll
        for (int j = 0; j < 4; j++) acc[i][j] = 0ull;

    float4 pa, pb[4];
    // prefetch chunk 0
    pa = *(const float4*)(Ab + (size_t)am * 256 + akq);
#pragma unroll
    for (int rep = 0; rep < 4; rep++)
        pb[rep] = *(const float4*)(Bb + (size_t)(n0 + bn0 + rep * 64) * 256 + bkq);

    for (int c = 0; c < 16; c++) {
        // store prefetched chunk to smem
        *(unsigned long long*)&As[akq + 0][2 * am] = pack2(pa.x, pa.x);
        *(unsigned long long*)&As[akq + 1][2 * am] = pack2(pa.y, pa.y);
        *(unsigned long long*)&As[akq + 2][2 * am] = pack2(pa.z, pa.z);
        *(unsigned long long*)&As[akq + 3][2 * am] = pack2(pa.w, pa.w);
#pragma unroll
        for (int rep = 0; rep < 4; rep++) {
            int n = bn0 + rep * 64;
            Bs[bkq + 0][n] = pb[rep].x; Bs[bkq + 1][n] = pb[rep].y;
            Bs[bkq + 2][n] = pb[rep].z; Bs[bkq + 3][n] = pb[rep].w;
        }
        __syncthreads();
        if (c < 15) {           // prefetch next chunk (hidden under mma)
            int k0 = (c + 1) * 16;
            pa = *(const float4*)(Ab + (size_t)am * 256 + k0 + akq);
#pragma unroll
            for (int rep = 0; rep < 4; rep++)
                pb[rep] = *(const float4*)(Bb + (size_t)(n0 + bn0 + rep * 64) * 256 + k0 + bkq);
        }
        mma_wide(As, Bs, acc, tn, tm);
        __syncthreads();
    }

#pragma unroll
    for (int i = 0; i < 8; i++) {
        int m = tm * 8 + i;
        float rb = rowBias ? rowBias[m] : 0.f;
        F2U u0, u1, u2, u3;
        u0.u = acc[i][0]; u1.u = acc[i][1]; u2.u = acc[i][2]; u3.u = acc[i][3];
        *(float4*)(Cb + (size_t)m * ldc + n0 + tn * 4) =
            make_float4(u0.f.x + rb, u0.f.y + rb, u1.f.x + rb, u1.f.y + rb);
        *(float4*)(Cb + (size_t)m * ldc + n0 + 128 + tn * 4) =
            make_float4(u2.f.x + rb, u2.f.y + rb, u3.f.x + rb, u3.f.y + rb);
    }
}

// =====================================================================
// K2: per-(b,m) softmax stats, two-pass (max, then sumexp; 2nd pass L2-hit)
// =====================================================================
__global__ __launch_bounds__(256) void softmax_stats()
{
    const float* p = g_logits + (size_t)blockIdx.x * N_;
    const int t = threadIdx.x;
    __shared__ float red[256];

    float mx = -1e30f;
    for (int i = t * 4; i < N_; i += 1024) {
        float4 v = *(const float4*)(p + i);
        mx = fmaxf(mx, fmaxf(fmaxf(v.x, v.y), fmaxf(v.z, v.w)));
    }
    red[t] = mx;
    __syncthreads();
    for (int s = 128; s > 0; s >>= 1) {
        if (t < s) red[t] = fmaxf(red[t], red[t + s]);
        __syncthreads();
    }
    const float gm = red[0];
    __syncthreads();

    float sm = 0.f;
    for (int i = t * 4; i < N_; i += 1024) {
        float4 v = *(const float4*)(p + i);
        sm += __expf(v.x - gm) + __expf(v.y - gm) + __expf(v.z - gm) + __expf(v.w - gm);
    }
    red[t] = sm;
    __syncthreads();
    for (int s = 128; s > 0; s >>= 1) {
        if (t < s) red[t] += red[t + s];
        __syncthreads();
    }
    if (t == 0) g_c[blockIdx.x] = gm + __logf(red[0]);
}

// =====================================================================
// K3: split-K pooling partials (pipelined). grid (32 splits, 1, 4 b)
// partial[b][s][m][d] = sum_{n in 512-split} exp(l[b,m,n]-c[b,m]) * x[b,n,d]
// =====================================================================
__global__ __launch_bounds__(256) void pool_partial(const float* __restrict__ x)
{
    const int b = blockIdx.z, s = blockIdx.x;
    const float* lg = g_logits + (size_t)b * M_ * N_;
    const float* xb = x + (size_t)b * N_ * D_;

    __shared__ float As[16][132];
    __shared__ float Bs[16][260];
    __shared__ float cs[64];

    const int tid = threadIdx.x;
    if (tid < 64) cs[tid] = g_c[b * 64 + tid];
    const int tn = tid & 31;
    const int tm = tid >> 5;
    const int am = tid >> 2, akq = (tid & 3) * 4;       // weights load coords
    const int xr = tid >> 6, xdq = (tid & 63) * 4;      // x load coords (4 reps)

    unsigned long long acc[8][4];
#pragma unroll
    for (int i = 0; i < 8; i++)
#pragma unroll
        for (int j = 0; j < 4; j++) acc[i][j] = 0ull;

    float4 pa, pb[4];
    {
        const int kbase = s * 512;
        pa = *(const float4*)(lg + (size_t)am * N_ + kbase + akq);
#pragma unroll
        for (int rep = 0; rep < 4; rep++)
            pb[rep] = *(const float4*)(xb + (size_t)(kbase + xr + rep * 4) * D_ + xdq);
    }
    __syncthreads();        // cs ready

    for (int nc = 0; nc < 32; nc++) {
        {   // store weights (exp) + x
            float cm = cs[am];
            float w0 = __expf(pa.x - cm), w1 = __expf(pa.y - cm);
            float w2 = __expf(pa.z - cm), w3 = __expf(pa.w - cm);
            *(unsigned long long*)&As[akq + 0][2 * am] = pack2(w0, w0);
            *(unsigned long long*)&As[akq + 1][2 * am] = pack2(w1, w1);
            *(unsigned long long*)&As[akq + 2][2 * am] = pack2(w2, w2);
            *(unsigned long long*)&As[akq + 3][2 * am] = pack2(w3, w3);
#pragma unroll
            for (int rep = 0; rep < 4; rep++)
                *(float4*)&Bs[xr + rep * 4][xdq] = pb[rep];
        }
        __syncthreads();
        if (nc < 31) {
            const int kbase = s * 512 + (nc + 1) * 16;
            pa = *(const float4*)(lg + (size_t)am * N_ + kbase + akq);
#pragma unroll
            for (int rep = 0; rep < 4; rep++)
                pb[rep] = *(const float4*)(xb + (size_t)(kbase + xr + rep * 4) * D_ + xdq);
        }
        mma_wide(As, Bs, acc, tn, tm);
        __syncthreads();
    }

    float* P = g_part + (size_t)(b * S2_ + s) * M_ * D_;
#pragma unroll
    for (int i = 0; i < 8; i++) {
        int m = tm * 8 + i;
        F2U u0, u1, u2, u3;
        u0.u = acc[i][0]; u1.u = acc[i][1]; u2.u = acc[i][2]; u3.u = acc[i][3];
        *(float4*)(P + (size_t)m * D_ + tn * 4) =
            make_float4(u0.f.x, u0.f.y, u1.f.x, u1.f.y);
        *(float4*)(P + (size_t)m * D_ + 128 + tn * 4) =
            make_float4(u2.f.x, u2.f.y, u3.f.x, u3.f.y);
    }
}

// K4: deterministic split-K reduce -> tokens (vectorized, full-chip grid)
__global__ __launch_bounds__(128) void pool_reduce()
{
    int idx4 = blockIdx.x * 128 + threadIdx.x;    // < B*M*D/4 = 16384
    int b = idx4 >> 12;
    int r4 = idx4 & 4095;
    const float4* p = (const float4*)(g_part + (size_t)b * S2_ * (M_ * D_)) + r4;
    float4 s = make_float4(0.f, 0.f, 0.f, 0.f);
#pragma unroll
    for (int i = 0; i < S2_; i++) {
        float4 v = p[(size_t)i * (M_ * D_ / 4)];
        s.x += v.x; s.y += v.y; s.z += v.z; s.w += v.w;
    }
    ((float4*)g_tokens)[idx4] = s;
}

// =====================================================================
// K5/K6 narrow GEMM (64x128 tile) for qkv / out-proj (tiny; unpipelined)
// =====================================================================
__device__ __forceinline__ void mma_tile(const float (*As)[132], const float (*Bs)[132],
                                         unsigned long long acc[8][2], int tn, int wm) {
#pragma unroll
    for (int kk = 0; kk < 32; kk++) {
        const ulonglong2* ap = (const ulonglong2*)&As[kk][wm * 16];
        ulonglong2 a0 = ap[0], a1 = ap[1], a2 = ap[2], a3 = ap[3];
        ulonglong2 bv = *(const ulonglong2*)&Bs[kk][tn * 4];
        fma2(acc[0][0], a0.x, bv.x); fma2(acc[0][1], a0.x, bv.y);
        fma2(acc[1][0], a0.y, bv.x); fma2(acc[1][1], a0.y, bv.y);
        fma2(acc[2][0], a1.x, bv.x); fma2(acc[2][1], a1.x, bv.y);
        fma2(acc[3][0], a1.y, bv.x); fma2(acc[3][1], a1.y, bv.y);
        fma2(acc[4][0], a2.x, bv.x); fma2(acc[4][1], a2.x, bv.y);
        fma2(acc[5][0], a2.y, bv.x); fma2(acc[5][1], a2.y, bv.y);
        fma2(acc[6][0], a3.x, bv.x); fma2(acc[6][1], a3.x, bv.y);
        fma2(acc[7][0], a3.y, bv.x); fma2(acc[7][1], a3.y, bv.y);
    }
}

__global__ __launch_bounds__(256) void gemm64_nt(
    const float* __restrict__ A, const float* __restrict__ Bm, float* __restrict__ C,
    int ldc, size_t aStride, size_t bStride, size_t cStride,
    const float* __restrict__ rowBias, const float* __restrict__ colBias)
{
    const float* Ab = A + (size_t)blockIdx.z * aStride;
    const float* Bb = Bm + (size_t)blockIdx.z * bStride;
    float* Cb = C + (size_t)blockIdx.z * cStride;
    const int n0 = blockIdx.x * 128;

    __shared__ float As[32][132];
    __shared__ float Bs[32][132];

    const int tid = threadIdx.x;
    const int tn = tid & 31;
    const int wm = tid >> 5;

    unsigned long long acc[8][2];
#pragma unroll
    for (int i = 0; i < 8; i++) { acc[i][0] = 0ull; acc[i][1] = 0ull; }

    for (int k0 = 0; k0 < 256; k0 += 32) {
#pragma unroll
        for (int rep = 0; rep < 2; rep++) {
            int id = tid + rep * 256;
            int m = id >> 3;
            int kq = (id & 7) * 4;
            float4 v = *(const float4*)(Ab + (size_t)m * 256 + k0 + kq);
            *(unsigned long long*)&As[kq + 0][2 * m] = pack2(v.x, v.x);
            *(unsigned long long*)&As[kq + 1][2 * m] = pack2(v.y, v.y);
            *(unsigned long long*)&As[kq + 2][2 * m] = pack2(v.z, v.z);
            *(unsigned long long*)&As[kq + 3][2 * m] = pack2(v.w, v.w);
        }
#pragma unroll
        for (int rep = 0; rep < 4; rep++) {
            int id = tid + rep * 256;
            int n = id >> 3;
            int kq = (id & 7) * 4;
            float4 v = *(const float4*)(Bb + (size_t)(n0 + n) * 256 + k0 + kq);
            Bs[kq + 0][n] = v.x; Bs[kq + 1][n] = v.y;
            Bs[kq + 2][n] = v.z; Bs[kq + 3][n] = v.w;
        }
        __syncthreads();
        mma_tile(As, Bs, acc, tn, wm);
        __syncthreads();
    }

    float cb0 = 0.f, cb1 = 0.f, cb2 = 0.f, cb3 = 0.f;
    if (colBias) {
        float4 cb = *(const float4*)(colBias + n0 + tn * 4);
        cb0 = cb.x; cb1 = cb.y; cb2 = cb.z; cb3 = cb.w;
    }
#pragma unroll
    for (int i = 0; i < 8; i++) {
        int m = wm * 8 + i;
        float rb = rowBias ? rowBias[m] : 0.f;
        F2U u0, u1; u0.u = acc[i][0]; u1.u = acc[i][1];
        *(float4*)(Cb + (size_t)m * ldc + n0 + tn * 4) =
            make_float4(u0.f.x + rb + cb0, u0.f.y + rb + cb1,
                        u1.f.x + rb + cb2, u1.f.y + rb + cb3);
    }
}

// =====================================================================
// Attention over M=64 tokens, per (b,h). 32 blocks x 64 threads.
// =====================================================================
__global__ __launch_bounds__(64) void attn_kernel()
{
    const int b = blockIdx.x >> 3, h = blockIdx.x & 7;
    __shared__ float ks[64][33], vs[64][33];
    const int t = threadIdx.x;
    const float* base = g_qkv + (size_t)b * M_ * 768 + h * 32;
    const float* kr = base + (size_t)t * 768 + 256;
    const float* vr = base + (size_t)t * 768 + 512;
#pragma unroll
    for (int j = 0; j < 32; j++) { ks[t][j] = kr[j]; vs[t][j] = vr[j]; }
    const float scale = 0.17677669529663687f;     // 1/sqrt(32)
    float q[32];
    const float* qr = base + (size_t)t * 768;
#pragma unroll
    for (int j = 0; j < 32; j++) q[j] = qr[j] * scale;
    __syncthreads();

    float sc[64]; float mx = -1e30f;
#pragma unroll
    for (int j = 0; j < 64; j++) {
        float s = 0.f;
#pragma unroll
        for (int d = 0; d < 32; d++) s += q[d] * ks[j][d];
        sc[j] = s; mx = fmaxf(mx, s);
    }
    float sum = 0.f;
#pragma unroll
    for (int j = 0; j < 64; j++) { sc[j] = __expf(sc[j] - mx); sum += sc[j]; }
    float inv = 1.f / sum;
    float o[32];
#pragma unroll
    for (int d = 0; d < 32; d++) o[d] = 0.f;
#pragma unroll
    for (int j = 0; j < 64; j++) {
        float p = sc[j] * inv;
#pragma unroll
        for (int d = 0; d < 32; d++) o[d] += p * vs[j][d];
    }
    float* op = g_attn + (size_t)b * M_ * D_ + (size_t)t * D_ + h * 32;
#pragma unroll
    for (int d = 0; d < 32; d++) op[d] = o[d];
}

// =====================================================================
// K7: unpooling (pipelined). out[b,n,d] = sum_m exp(l[b,m,n]-c[b,m])*tokout[b,m,d]
// tile 64n x 256d, K=64 (4 chunks). grid (256, 1, 4)
// =====================================================================
__global__ __launch_bounds__(256) void unpool_kernel(float* __restrict__ out)
{
    const int b = blockIdx.z;
    const int n0 = blockIdx.x * 64;
    const float* lg = g_logits + (size_t)b * M_ * N_;

    __shared__ float As[16][132];   // [k=m][2n dup]
    __shared__ float Bs[16][260];   // [k=m][d]
    __shared__ float cs[64];

    const int tid = threadIdx.x;
    if (tid < 64) cs[tid] = g_c[b * 64 + tid];
    const int tn = tid & 31;
    const int tm = tid >> 5;
    const int mrow = tid >> 4, n4 = (tid & 15) * 4;     // weights load coords
    const int br = tid >> 6, bdq = (tid & 63) * 4;      // tokout load coords

    unsigned long long acc[8][4];
#pragma unroll
    for (int i = 0; i < 8; i++)
#pragma unroll
        for (int j = 0; j < 4; j++) acc[i][j] = 0ull;

    float4 pa, pb[4];
    pa = *(const float4*)(lg + (size_t)mrow * N_ + n0 + n4);
#pragma unroll
    for (int rep = 0; rep < 4; rep++)
        pb[rep] = *(const float4*)(g_tokout + ((size_t)b * M_ + br + rep * 4) * D_ + bdq);
    __syncthreads();        // cs ready

    for (int c = 0; c < 4; c++) {
        {
            float cm = cs[c * 16 + mrow];
            float w0 = __expf(pa.x - cm), w1 = __expf(pa.y - cm);
            float w2 = __expf(pa.z - cm), w3 = __expf(pa.w - cm);
            *(unsigned long long*)&As[mrow][2 * (n4 + 0)] = pack2(w0, w0);
            *(unsigned long long*)&As[mrow][2 * (n4 + 1)] = pack2(w1, w1);
            *(unsigned long long*)&As[mrow][2 * (n4 + 2)] = pack2(w2, w2);
            *(unsigned long long*)&As[mrow][2 * (n4 + 3)] = pack2(w3, w3);
#pragma unroll
            for (int rep = 0; rep < 4; rep++)
                *(float4*)&Bs[br + rep * 4][bdq] = pb[rep];
        }
        __syncthreads();
        if (c < 3) {
            int k0 = (c + 1) * 16;
            pa = *(const float4*)(lg + (size_t)(k0 + mrow) * N_ + n0 + n4);
#pragma unroll
            for (int rep = 0; rep < 4; rep++)
                pb[rep] = *(const float4*)(g_tokout + ((size_t)b * M_ + k0 + br + rep * 4) * D_ + bdq);
        }
        mma_wide(As, Bs, acc, tn, tm);
        __syncthreads();
    }

#pragma unroll
    for (int i = 0; i < 8; i++) {
        int n = n0 + tm * 8 + i;
        F2U u0, u1, u2, u3;
        u0.u = acc[i][0]; u1.u = acc[i][1]; u2.u = acc[i][2]; u3.u = acc[i][3];
        *(float4*)(out + ((size_t)b * N_ + n) * D_ + tn * 4) =
            make_float4(u0.f.x, u0.f.y, u1.f.x, u1.f.y);
        *(float4*)(out + ((size_t)b * N_ + n) * D_ + 128 + tn * 4) =
            make_float4(u2.f.x, u2.f.y, u3.f.x, u3.f.y);
    }
}

// =====================================================================
extern "C" void kernel_launch(void* const* d_in, const int* in_sizes, int n_in,
                              void* d_out, int out_size)
{
    const float* x    = (const float*)d_in[0];
    const float* Ws   = (const float*)d_in[1];
    const float* bs   = (const float*)d_in[2];
    const float* Wqkv = (const float*)d_in[3];
    const float* Wo   = (const float*)d_in[4];
    const float* bo   = (const float*)d_in[5];
    float* out = (float*)d_out;

    float *lg, *tok, *qkv, *att, *tko;
    cudaGetSymbolAddress((void**)&lg,  g_logits);
    cudaGetSymbolAddress((void**)&tok, g_tokens);
    cudaGetSymbolAddress((void**)&qkv, g_qkv);
    cudaGetSymbolAddress((void**)&att, g_attn);
    cudaGetSymbolAddress((void**)&tko, g_tokout);

    // K1: logits[b][m][n] = Ws . x[b]^T + bs
    gemm64_wide<<<dim3(N_ / 256, 1, B_), 256>>>(
        Ws, x, lg, N_, 0, (size_t)N_ * D_, (size_t)M_ * N_, bs);
    // K2: softmax stats
    softmax_stats<<<B_ * M_, 256>>>();
    // K3/K4: pooling
    pool_partial<<<dim3(S2_, 1, B_), 256>>>(x);
    pool_reduce<<<128, 128>>>();
    // K5: qkv = tokens . Wqkv^T
    gemm64_nt<<<dim3(6, 1, B_), 256>>>(
        tok, Wqkv, qkv, 768, (size_t)M_ * D_, 0, (size_t)M_ * 768, nullptr, nullptr);
    // attention
    attn_kernel<<<B_ * H_, 64>>>();
    // K6: token_out = attn . Wo^T + bo
    gemm64_nt<<<dim3(2, 1, B_), 256>>>(
        att, Wo, tko, D_, (size_t)M_ * D_, 0, (size_t)M_ * D_, nullptr, bo);
    // K7: unpool
    unpool_kernel<<<dim3(N_ / 64, 1, B_), 256>>>(out);
}